// round 6
// baseline (speedup 1.0000x reference)
#include <cuda_runtime.h>
#include <cuda_fp16.h>
#include <cstdint>

#define N_NODES 102400
#define MAX_E   3276800
#define LATDIM  128
#define SLOTS   96         // Poisson(32): P(deg > 96) ~ 1e-18 per node
#define OVF_CAP 8192

// ---------------------------------------------------------------------------
// Device scratch (allocation-free). Zero-initialized at module load.
// INVARIANT: every kernel_launch leaves g_cursor[] == 0 and g_ovf_count == 0
// (k_agg re-zeroes cursors after reading; k_ovf re-zeroes the count), so no
// separate zeroing kernel is ever needed.
// ---------------------------------------------------------------------------
__device__ int     g_cursor[N_NODES];
__device__ int2    g_edge[(size_t)N_NODES * SLOTS];      // (col, f32 val bits)
__device__ __half2 g_hemb[(size_t)N_NODES * (LATDIM/2)]; // fp16 copy of embeds
__device__ int     g_ovf_count;
__device__ int4    g_ovf[OVF_CAP];                       // (row, col, val bits, 0)

// ---------------------------------------------------------------------------
// K1: fused convert + scatter.
//   Phase A (grid-stride): embeds f32 -> f16 into g_hemb (coalesced, hides in
//           phase B's wavefront-bound slack).
//   Phase B (grid-stride): bucket scatter, 4 edges/thread for 4 atomic
//           round-trips in flight. Cursors are zero on entry (invariant).
// ---------------------------------------------------------------------------
__global__ void k_conv_scatter(const int*   __restrict__ rows,
                               const int*   __restrict__ cols,
                               const float* __restrict__ vals,
                               const float* __restrict__ embeds,
                               int E) {
    const int i = blockIdx.x * blockDim.x + threadIdx.x;
    const int stride = gridDim.x * blockDim.x;

    // Phase A: convert embeds to fp16.
    const int NCONV = N_NODES * LATDIM / 4;   // float4 groups
    for (int k = i; k < NCONV; k += stride) {
        float4 f = __ldg(((const float4*)embeds) + k);
        __half2 h0 = __floats2half2_rn(f.x, f.y);
        __half2 h1 = __floats2half2_rn(f.z, f.w);
        uint2 packed;
        packed.x = *reinterpret_cast<uint32_t*>(&h0);
        packed.y = *reinterpret_cast<uint32_t*>(&h1);
        reinterpret_cast<uint2*>(g_hemb)[k] = packed;
    }

    // Phase B: scatter into fixed-capacity row buckets.
    const int E4 = E >> 2;
    for (int k = i; k < E4; k += stride) {
        int4   r = __ldg(((const int4*)  rows) + k);
        int4   c = __ldg(((const int4*)  cols) + k);
        float4 v = __ldg(((const float4*)vals) + k);
        int p0 = atomicAdd(&g_cursor[r.x], 1);
        int p1 = atomicAdd(&g_cursor[r.y], 1);
        int p2 = atomicAdd(&g_cursor[r.z], 1);
        int p3 = atomicAdd(&g_cursor[r.w], 1);

        #define EMIT(rr, pp, cc, vv)                                          \
            if (pp < SLOTS) {                                                 \
                g_edge[(size_t)(rr) * SLOTS + (pp)] =                         \
                    make_int2((cc), __float_as_int(vv));                      \
            } else {                                                          \
                int q = atomicAdd(&g_ovf_count, 1);                           \
                if (q < OVF_CAP)                                              \
                    g_ovf[q] = make_int4((rr), (cc), __float_as_int(vv), 0);  \
            }
        EMIT(r.x, p0, c.x, v.x)
        EMIT(r.y, p1, c.y, v.y)
        EMIT(r.z, p2, c.z, v.z)
        EMIT(r.w, p3, c.w, v.w)
    }
    for (int e = (E4 << 2) + i; e < E; e += stride) {
        int rr = rows[e];
        int p = atomicAdd(&g_cursor[rr], 1);
        EMIT(rr, p, cols[e], vals[e])
    }
    #undef EMIT
}

// ---------------------------------------------------------------------------
// K2: warp-per-node aggregation over fp16 embeds, fp32 accumulators.
// Coalesced edge loads + shfl broadcast -> 32 independent 8B gathers/warp.
// Also re-zeroes this node's cursor for the next launch (invariant).
// ---------------------------------------------------------------------------
__global__ void __launch_bounds__(256) k_agg(float* __restrict__ out) {
    const int node = (blockIdx.x * blockDim.x + threadIdx.x) >> 5;
    const int lane = threadIdx.x & 31;
    if (node >= N_NODES) return;

    int cnt = g_cursor[node];
    if (lane == 0) g_cursor[node] = 0;        // recycle for next launch
    if (cnt > SLOTS) cnt = SLOTS;
    const int2* bucket = g_edge + (size_t)node * SLOTS;

    float4 acc = make_float4(0.f, 0.f, 0.f, 0.f);

    int base = 0;
    for (; base + 32 <= cnt; base += 32) {
        int2 ev = __ldg(bucket + base + lane);
        #pragma unroll 8
        for (int j = 0; j < 32; j++) {
            int   c = __shfl_sync(0xffffffffu, ev.x, j);
            float v = __int_as_float(__shfl_sync(0xffffffffu, ev.y, j));
            uint2 h = __ldg(reinterpret_cast<const uint2*>(
                          g_hemb + (size_t)c * (LATDIM / 2)) + lane);
            __half2 h0 = *reinterpret_cast<__half2*>(&h.x);
            __half2 h1 = *reinterpret_cast<__half2*>(&h.y);
            float2 f0 = __half22float2(h0);
            float2 f1 = __half22float2(h1);
            acc.x = fmaf(v, f0.x, acc.x);
            acc.y = fmaf(v, f0.y, acc.y);
            acc.z = fmaf(v, f1.x, acc.z);
            acc.w = fmaf(v, f1.y, acc.w);
        }
    }
    const int n = cnt - base;
    if (n > 0) {
        int2 ev = (lane < n) ? __ldg(bucket + base + lane) : make_int2(0, 0);
        for (int j = 0; j < n; j++) {
            int   c = __shfl_sync(0xffffffffu, ev.x, j);
            float v = __int_as_float(__shfl_sync(0xffffffffu, ev.y, j));
            uint2 h = __ldg(reinterpret_cast<const uint2*>(
                          g_hemb + (size_t)c * (LATDIM / 2)) + lane);
            __half2 h0 = *reinterpret_cast<__half2*>(&h.x);
            __half2 h1 = *reinterpret_cast<__half2*>(&h.y);
            float2 f0 = __half22float2(h0);
            float2 f1 = __half22float2(h1);
            acc.x = fmaf(v, f0.x, acc.x);
            acc.y = fmaf(v, f0.y, acc.y);
            acc.z = fmaf(v, f1.x, acc.z);
            acc.w = fmaf(v, f1.y, acc.w);
        }
    }

    *reinterpret_cast<float4*>(out + (size_t)node * LATDIM + lane * 4) = acc;
}

// ---------------------------------------------------------------------------
// K3: overflow cleanup (expected count: 0). SINGLE BLOCK so that reading the
// count and re-zeroing it can be ordered by __syncthreads. fp32 gather +
// vector RED (adds on top of k_agg's stored rows).
// ---------------------------------------------------------------------------
__global__ void __launch_bounds__(256) k_ovf(const float* __restrict__ embeds,
                                             float* __restrict__ out) {
    __shared__ int s_cnt;
    if (threadIdx.x == 0) {
        int c = g_ovf_count;
        s_cnt = (c > OVF_CAP) ? OVF_CAP : c;
        g_ovf_count = 0;                      // recycle for next launch
    }
    __syncthreads();
    const int cnt = s_cnt;
    if (cnt == 0) return;

    const int warp = threadIdx.x >> 5;        // 8 warps
    const int lane = threadIdx.x & 31;
    for (int e = warp; e < cnt; e += 8) {
        int4 t = g_ovf[e];
        float v = __int_as_float(t.z);
        float4 x = __ldg(reinterpret_cast<const float4*>(
                       embeds + (size_t)t.y * LATDIM) + lane);
        float* dst = out + (size_t)t.x * LATDIM + lane * 4;
        asm volatile(
            "red.global.add.v4.f32 [%0], {%1, %2, %3, %4};"
            :: "l"(dst), "f"(v * x.x), "f"(v * x.y), "f"(v * x.z), "f"(v * x.w)
            : "memory");
    }
}

// ---------------------------------------------------------------------------
// kernel_launch
// Inputs: d_in[0] adj_indices int32 [2,E]; d_in[1] adj_values f32 [E];
//         d_in[2] embeds f32 [N,128]; d_in[3] batch_size (unused).
// Output: f32 [N,128] — every row written by k_agg; k_ovf RED-adds leftovers.
// ---------------------------------------------------------------------------
extern "C" void kernel_launch(void* const* d_in, const int* in_sizes, int n_in,
                              void* d_out, int out_size)
{
    int E = in_sizes[0] / 2;
    if (E > MAX_E) E = MAX_E;

    const int*   idx    = (const int*)  d_in[0];
    const float* vals   = (const float*)d_in[1];
    const float* embeds = (const float*)d_in[2];
    float*       out    = (float*)      d_out;

    const int* rows = idx;
    const int* cols = idx + E;

    k_conv_scatter<<<148 * 16, 256>>>(rows, cols, vals, embeds, E);
    k_agg<<<N_NODES / 8, 256>>>(out);
    k_ovf<<<1, 256>>>(embeds, out);
}

// round 7
// speedup vs baseline: 2.0956x; 2.0956x over previous
#include <cuda_runtime.h>
#include <cuda_fp16.h>
#include <cstdint>

#define N_NODES 102400
#define MAX_E   3276800
#define LATDIM  128
#define SLOTS   96         // Poisson(32): P(deg > 96) ~ 1e-18 per node
#define OVF_CAP 8192

// ---------------------------------------------------------------------------
// Device scratch (allocation-free).
// ---------------------------------------------------------------------------
__device__ int     g_cursor[N_NODES];
__device__ int2    g_edge[(size_t)N_NODES * SLOTS];      // (col, f32 val bits)
__device__ __half2 g_hemb[(size_t)N_NODES * (LATDIM/2)]; // fp16 copy of embeds
__device__ int     g_ovf_count;
__device__ int4    g_ovf[OVF_CAP];                       // (row, col, val bits, 0)

// ---------------------------------------------------------------------------
// K1: prep — zero cursors/overflow counter AND convert embeds f32 -> f16.
// (Separate kernel: round-6 showed fusing this into scatter serializes in
// front of the scatter loop and regresses the pipeline.)
// ---------------------------------------------------------------------------
__global__ void k_prep(const float* __restrict__ embeds) {
    const int i = blockIdx.x * blockDim.x + threadIdx.x;
    const int stride = gridDim.x * blockDim.x;

    const int NCONV = N_NODES * LATDIM / 4;   // float4 groups
    for (int k = i; k < NCONV; k += stride) {
        float4 f = __ldg(((const float4*)embeds) + k);
        __half2 h0 = __floats2half2_rn(f.x, f.y);
        __half2 h1 = __floats2half2_rn(f.z, f.w);
        uint2 packed;
        packed.x = *reinterpret_cast<uint32_t*>(&h0);
        packed.y = *reinterpret_cast<uint32_t*>(&h1);
        reinterpret_cast<uint2*>(g_hemb)[k] = packed;
    }
    for (int k = i; k < N_NODES; k += stride) g_cursor[k] = 0;
    if (i == 0) g_ovf_count = 0;
}

// ---------------------------------------------------------------------------
// K2: single-pass bucket scatter. 4 edges/thread keeps 4 atomic round-trips
// in flight. Overflow (essentially never taken) goes to a side list.
// ---------------------------------------------------------------------------
__global__ void k_scatter(const int*   __restrict__ rows,
                          const int*   __restrict__ cols,
                          const float* __restrict__ vals,
                          int E) {
    const int E4 = E >> 2;
    const int i = blockIdx.x * blockDim.x + threadIdx.x;
    const int stride = gridDim.x * blockDim.x;

    for (int k = i; k < E4; k += stride) {
        int4   r = __ldg(((const int4*)  rows) + k);
        int4   c = __ldg(((const int4*)  cols) + k);
        float4 v = __ldg(((const float4*)vals) + k);
        int p0 = atomicAdd(&g_cursor[r.x], 1);
        int p1 = atomicAdd(&g_cursor[r.y], 1);
        int p2 = atomicAdd(&g_cursor[r.z], 1);
        int p3 = atomicAdd(&g_cursor[r.w], 1);

        #define EMIT(rr, pp, cc, vv)                                          \
            if (pp < SLOTS) {                                                 \
                g_edge[(size_t)(rr) * SLOTS + (pp)] =                         \
                    make_int2((cc), __float_as_int(vv));                      \
            } else {                                                          \
                int q = atomicAdd(&g_ovf_count, 1);                           \
                if (q < OVF_CAP)                                              \
                    g_ovf[q] = make_int4((rr), (cc), __float_as_int(vv), 0);  \
            }
        EMIT(r.x, p0, c.x, v.x)
        EMIT(r.y, p1, c.y, v.y)
        EMIT(r.z, p2, c.z, v.z)
        EMIT(r.w, p3, c.w, v.w)
    }
    for (int e = (E4 << 2) + i; e < E; e += stride) {
        int rr = rows[e];
        int p = atomicAdd(&g_cursor[rr], 1);
        EMIT(rr, p, cols[e], vals[e])
    }
    #undef EMIT
}

// ---------------------------------------------------------------------------
// K3: warp-per-node aggregation over fp16 embeds, fp32 accumulators.
// Coalesced edge loads + shfl broadcast -> 32 independent 8B gathers/warp.
// Overflow handling is INLINE: a warp whose degree exceeded SLOTS scans the
// (tiny, normally empty) side list for its own row. No extra kernel launch.
// ---------------------------------------------------------------------------
__global__ void __launch_bounds__(256) k_agg(float* __restrict__ out) {
    const int node = (blockIdx.x * blockDim.x + threadIdx.x) >> 5;
    const int lane = threadIdx.x & 31;
    if (node >= N_NODES) return;

    const int raw_cnt = g_cursor[node];
    const int cnt = (raw_cnt > SLOTS) ? SLOTS : raw_cnt;
    const int2* bucket = g_edge + (size_t)node * SLOTS;

    float4 acc = make_float4(0.f, 0.f, 0.f, 0.f);

    int base = 0;
    for (; base + 32 <= cnt; base += 32) {
        int2 ev = __ldg(bucket + base + lane);
        #pragma unroll 8
        for (int j = 0; j < 32; j++) {
            int   c = __shfl_sync(0xffffffffu, ev.x, j);
            float v = __int_as_float(__shfl_sync(0xffffffffu, ev.y, j));
            uint2 h = __ldg(reinterpret_cast<const uint2*>(
                          g_hemb + (size_t)c * (LATDIM / 2)) + lane);
            __half2 h0 = *reinterpret_cast<__half2*>(&h.x);
            __half2 h1 = *reinterpret_cast<__half2*>(&h.y);
            float2 f0 = __half22float2(h0);
            float2 f1 = __half22float2(h1);
            acc.x = fmaf(v, f0.x, acc.x);
            acc.y = fmaf(v, f0.y, acc.y);
            acc.z = fmaf(v, f1.x, acc.z);
            acc.w = fmaf(v, f1.y, acc.w);
        }
    }
    {
        const int n = cnt - base;
        if (n > 0) {
            int2 ev = (lane < n) ? __ldg(bucket + base + lane) : make_int2(0, 0);
            for (int j = 0; j < n; j++) {
                int   c = __shfl_sync(0xffffffffu, ev.x, j);
                float v = __int_as_float(__shfl_sync(0xffffffffu, ev.y, j));
                uint2 h = __ldg(reinterpret_cast<const uint2*>(
                              g_hemb + (size_t)c * (LATDIM / 2)) + lane);
                __half2 h0 = *reinterpret_cast<__half2*>(&h.x);
                __half2 h1 = *reinterpret_cast<__half2*>(&h.y);
                float2 f0 = __half22float2(h0);
                float2 f1 = __half22float2(h1);
                acc.x = fmaf(v, f0.x, acc.x);
                acc.y = fmaf(v, f0.y, acc.y);
                acc.z = fmaf(v, f1.x, acc.z);
                acc.w = fmaf(v, f1.y, acc.w);
            }
        }
    }

    // Overflow safety net (dead code for this dataset; correctness guarantee).
    if (raw_cnt > SLOTS) {
        int ocnt = g_ovf_count;
        if (ocnt > OVF_CAP) ocnt = OVF_CAP;
        for (int e = 0; e < ocnt; e++) {
            int4 t = g_ovf[e];                // broadcast load, all lanes same
            if (t.x == node) {
                float v = __int_as_float(t.z);
                uint2 h = __ldg(reinterpret_cast<const uint2*>(
                              g_hemb + (size_t)t.y * (LATDIM / 2)) + lane);
                __half2 h0 = *reinterpret_cast<__half2*>(&h.x);
                __half2 h1 = *reinterpret_cast<__half2*>(&h.y);
                float2 f0 = __half22float2(h0);
                float2 f1 = __half22float2(h1);
                acc.x = fmaf(v, f0.x, acc.x);
                acc.y = fmaf(v, f0.y, acc.y);
                acc.z = fmaf(v, f1.x, acc.z);
                acc.w = fmaf(v, f1.y, acc.w);
            }
        }
    }

    *reinterpret_cast<float4*>(out + (size_t)node * LATDIM + lane * 4) = acc;
}

// ---------------------------------------------------------------------------
// kernel_launch
// Inputs: d_in[0] adj_indices int32 [2,E]; d_in[1] adj_values f32 [E];
//         d_in[2] embeds f32 [N,128]; d_in[3] batch_size (unused).
// Output: f32 [N,128] — every row written exactly once by k_agg.
// ---------------------------------------------------------------------------
extern "C" void kernel_launch(void* const* d_in, const int* in_sizes, int n_in,
                              void* d_out, int out_size)
{
    int E = in_sizes[0] / 2;
    if (E > MAX_E) E = MAX_E;

    const int*   idx    = (const int*)  d_in[0];
    const float* vals   = (const float*)d_in[1];
    const float* embeds = (const float*)d_in[2];
    float*       out    = (float*)      d_out;

    const int* rows = idx;
    const int* cols = idx + E;

    k_prep<<<148 * 16, 256>>>(embeds);
    k_scatter<<<148 * 16, 256>>>(rows, cols, vals, E);
    k_agg<<<N_NODES / 8, 256>>>(out);
}